// round 1
// baseline (speedup 1.0000x reference)
#include <cuda_runtime.h>
#include <stdint.h>

#define N_NODES 10242
#define NNZ_MAX 71694
#define BT      32          // B*T
#define C_IN    16
#define F       512         // C_IN * BT
#define KS      20
#define COUT    32

typedef unsigned long long ull;

// ---------------- device scratch (no runtime allocation allowed) ----------------
__device__ float g_xs[(size_t)KS * N_NODES * F];   // all Chebyshev slices, ~420MB
__device__ int   g_cnt[N_NODES];
__device__ int   g_rowptr[N_NODES + 1];
__device__ int   g_cursor[N_NODES];
__device__ int   g_colidx[NNZ_MAX];
__device__ float g_vals[NNZ_MAX];
__device__ float g_Wt[C_IN * KS * COUT];           // W transposed: [ck][cout]

// ---------------- CSR build ----------------
__global__ void zero_cnt_kernel() {
    int i = blockIdx.x * blockDim.x + threadIdx.x;
    if (i < N_NODES) g_cnt[i] = 0;
}

__global__ void csr_count_kernel(const int* __restrict__ erow, int nnz) {
    int e = blockIdx.x * blockDim.x + threadIdx.x;
    if (e < nnz) atomicAdd(&g_cnt[erow[e]], 1);
}

__global__ void csr_scan_kernel(int nnz) {
    __shared__ int sm[1024];
    int t = threadIdx.x;
    const int CH = 11;                       // 1024*11 = 11264 >= 10242
    int base = t * CH;
    int s = 0;
#pragma unroll
    for (int i = 0; i < CH; ++i) {
        int idx = base + i;
        if (idx < N_NODES) s += g_cnt[idx];
    }
    sm[t] = s;
    __syncthreads();
    for (int off = 1; off < 1024; off <<= 1) {
        int v = (t >= off) ? sm[t - off] : 0;
        __syncthreads();
        sm[t] += v;
        __syncthreads();
    }
    int run = sm[t] - s;                     // exclusive prefix at chunk start
#pragma unroll
    for (int i = 0; i < CH; ++i) {
        int idx = base + i;
        if (idx < N_NODES) {
            g_rowptr[idx] = run;
            g_cursor[idx] = run;
            run += g_cnt[idx];
        }
    }
    if (t == 0) g_rowptr[N_NODES] = nnz;
}

__global__ void csr_scatter_kernel(const int* __restrict__ erow,
                                   const int* __restrict__ ecol,
                                   const float* __restrict__ eval, int nnz) {
    int e = blockIdx.x * blockDim.x + threadIdx.x;
    if (e < nnz) {
        int r = erow[e];
        int p = atomicAdd(&g_cursor[r], 1);
        g_colidx[p] = ecol[e];
        g_vals[p]   = eval[e];
    }
}

// Canonical per-row order (col asc, then val asc) -> deterministic fp sums
// regardless of atomic scatter order.
__global__ void csr_sort_kernel() {
    int r = blockIdx.x * blockDim.x + threadIdx.x;
    if (r >= N_NODES) return;
    int s = g_rowptr[r], e = g_rowptr[r + 1];
    for (int i = s + 1; i < e; ++i) {
        int   kc = g_colidx[i];
        float kv = g_vals[i];
        int j = i - 1;
        while (j >= s && (g_colidx[j] > kc || (g_colidx[j] == kc && g_vals[j] > kv))) {
            g_colidx[j + 1] = g_colidx[j];
            g_vals[j + 1]   = g_vals[j];
            --j;
        }
        g_colidx[j + 1] = kc;
        g_vals[j + 1]   = kv;
    }
}

// ---------------- W transpose: g_Wt[ck*COUT + cout] = W[cout*CK + ck] ----------------
__global__ void wt_build_kernel(const float* __restrict__ W) {
    int i = blockIdx.x * blockDim.x + threadIdx.x;
    const int CK = C_IN * KS;
    if (i < COUT * CK) {
        int cout = i / CK;
        int ck   = i % CK;
        g_Wt[ck * COUT + cout] = W[i];
    }
}

// ---------------- x [BT,N,C] -> xs slice 0 [N, c*BT+bt] ----------------
__global__ void transpose_kernel(const float* __restrict__ x) {
    __shared__ float sm[F];
    int n = blockIdx.x;
    for (int t = threadIdx.x; t < F; t += blockDim.x) {
        int bt = t >> 4;          // 0..31
        int c  = t & 15;          // 0..15
        sm[c * BT + bt] = x[((size_t)bt * N_NODES + n) * C_IN + c];
    }
    __syncthreads();
    for (int t = threadIdx.x; t < F; t += blockDim.x)
        g_xs[(size_t)n * F + t] = sm[t];
}

// ---------------- SpMM step: out = (first ? L*cur : 2*L*cur - prev) ----------------
__global__ void __launch_bounds__(128) spmm_kernel(int kc, int kp, int ko, int first) {
    int n = blockIdx.x;
    int t = threadIdx.x;   // 0..127, each handles float4 (4 features)
    const float4* cur = (const float4*)(g_xs + (size_t)kc * N_NODES * F);
    float4*       dst = (float4*)      (g_xs + (size_t)ko * N_NODES * F);
    int s = g_rowptr[n], e = g_rowptr[n + 1];
    float4 acc = make_float4(0.f, 0.f, 0.f, 0.f);
    for (int i = s; i < e; ++i) {
        int   col = g_colidx[i];
        float v   = g_vals[i];
        float4 u  = __ldg(&cur[(size_t)col * 128 + t]);
        acc.x = fmaf(v, u.x, acc.x);
        acc.y = fmaf(v, u.y, acc.y);
        acc.z = fmaf(v, u.z, acc.z);
        acc.w = fmaf(v, u.w, acc.w);
    }
    size_t o = (size_t)n * 128 + t;
    if (first) {
        dst[o] = acc;
    } else {
        const float4* prev = (const float4*)(g_xs + (size_t)kp * N_NODES * F);
        float4 p = prev[o];
        dst[o] = make_float4(2.f * acc.x - p.x, 2.f * acc.y - p.y,
                             2.f * acc.z - p.z, 2.f * acc.w - p.w);
    }
}

// ---------------- final projection, packed f32x2 FFMA ----------------
__device__ __forceinline__ void ffma2(ull& d, ull a, ull b) {
    asm("fma.rn.f32x2 %0, %1, %2, %0;" : "+l"(d) : "l"(a), "l"(b));
}

__global__ void __launch_bounds__(128) gemm_kernel(float* __restrict__ out) {
    extern __shared__ float sh[];
    float* sx  = sh;                 // KS*F   = 10240 floats (40KB)
    float* wsm = sh + KS * F;        // CK*COUT= 10240 floats (40KB)
    int n   = blockIdx.x;
    int tid = threadIdx.x;           // 128 threads

    // stage this node's 20 slices
#pragma unroll
    for (int k = 0; k < KS; ++k) {
        const float4* src = (const float4*)(g_xs + (size_t)k * N_NODES * F + (size_t)n * F);
        ((float4*)(sx + k * F))[tid] = src[tid];       // 128 float4 = 512 floats
    }
    // stage W^T (L1/L2-cached global, 40KB)
    const float4* wsrc = (const float4*)g_Wt;
    for (int i = tid; i < (C_IN * KS * COUT) / 4; i += 128)
        ((float4*)wsm)[i] = wsrc[i];
    __syncthreads();

    int bt = tid & 31;               // feature batch index
    int cg = tid >> 5;               // 0..3 -> couts [cg*8, cg*8+8)
    ull a0 = 0ull, a1 = 0ull, a2 = 0ull, a3 = 0ull;

#pragma unroll 2
    for (int k = 0; k < KS; ++k) {
#pragma unroll
        for (int c = 0; c < C_IN; ++c) {
            float sv = sx[k * F + c * BT + bt];
            ull s2;
            asm("mov.b64 %0, {%1, %1};" : "=l"(s2) : "f"(sv));
            const ull* wp = (const ull*)&wsm[(c * KS + k) * COUT + cg * 8];
            ffma2(a0, s2, wp[0]);
            ffma2(a1, s2, wp[1]);
            ffma2(a2, s2, wp[2]);
            ffma2(a3, s2, wp[3]);
        }
    }

    float r0x, r0y, r1x, r1y, r2x, r2y, r3x, r3y;
    asm("mov.b64 {%0, %1}, %2;" : "=f"(r0x), "=f"(r0y) : "l"(a0));
    asm("mov.b64 {%0, %1}, %2;" : "=f"(r1x), "=f"(r1y) : "l"(a1));
    asm("mov.b64 {%0, %1}, %2;" : "=f"(r2x), "=f"(r2y) : "l"(a2));
    asm("mov.b64 {%0, %1}, %2;" : "=f"(r3x), "=f"(r3y) : "l"(a3));

    size_t o = ((size_t)bt * N_NODES + n) * COUT + cg * 8;
    *(float4*)&out[o]     = make_float4(r0x, r0y, r1x, r1y);
    *(float4*)&out[o + 4] = make_float4(r2x, r2y, r3x, r3y);
}

// ---------------- launch ----------------
extern "C" void kernel_launch(void* const* d_in, const int* in_sizes, int n_in,
                              void* d_out, int out_size) {
    const float* x    = (const float*)d_in[0];
    const int*   erow = (const int*)  d_in[1];
    const int*   ecol = (const int*)  d_in[2];
    const float* eval = (const float*)d_in[3];
    const float* W    = (const float*)d_in[4];
    float*       out  = (float*)d_out;
    int nnz = in_sizes[1];
    if (nnz > NNZ_MAX) nnz = NNZ_MAX;

    const int SMEM = 2 * KS * F * (int)sizeof(float);   // 81920 B
    cudaFuncSetAttribute(gemm_kernel, cudaFuncAttributeMaxDynamicSharedMemorySize, SMEM);

    zero_cnt_kernel   <<<(N_NODES + 255) / 256, 256>>>();
    csr_count_kernel  <<<(nnz + 255) / 256, 256>>>(erow, nnz);
    csr_scan_kernel   <<<1, 1024>>>(nnz);
    csr_scatter_kernel<<<(nnz + 255) / 256, 256>>>(erow, ecol, eval, nnz);
    csr_sort_kernel   <<<(N_NODES + 127) / 128, 128>>>();
    wt_build_kernel   <<<(COUT * C_IN * KS + 255) / 256, 256>>>(W);

    transpose_kernel  <<<N_NODES, 256>>>(x);            // slice 0
    spmm_kernel       <<<N_NODES, 128>>>(0, 0, 1, 1);   // slice 1 = L x0
    for (int k = 2; k < KS; ++k)
        spmm_kernel   <<<N_NODES, 128>>>(k - 1, k - 2, k, 0);

    gemm_kernel       <<<N_NODES, 128, SMEM>>>(out);
}